// round 10
// baseline (speedup 1.0000x reference)
#include <cuda_runtime.h>

#define BB   4
#define NN   8000
#define CC   64
#define KK   32
#define DD   9
#define NCLS 13
#define BN   (BB*NN)

#define CAP    128        // per-thread candidate buffer slots (1KB local)
#define CHUNK  2000       // candidates per smem chunk (32KB) -> 4 chunks

__device__ float  g_G1[BN*CC];
__device__ float  g_G2[BN*CC];
__device__ float4 g_pts[BN];
__device__ int    g_idx[BN*KK];

__device__ __forceinline__ float inf_f() { return __int_as_float(0x7f800000); }

// ---------------------------------------------------------------------------
// Encoder (measured-best R1: block=256, 161 regs, ~101us):
// feats = relu(x@w1+b1)@w2+b2 ; G1 = feats@f1w ; G2 = feats@f2w
// ---------------------------------------------------------------------------
__global__ __launch_bounds__(256) void encoder_kernel(
    const float* __restrict__ x,
    const float* __restrict__ w1, const float* __restrict__ b1v,
    const float* __restrict__ w2, const float* __restrict__ b2v,
    const float* __restrict__ f1w, const float* __restrict__ f2w)
{
    int g = blockIdx.x * blockDim.x + threadIdx.x;
    if (g >= BN) return;

    float xr[DD];
    #pragma unroll
    for (int d = 0; d < DD; d++) xr[d] = x[g*DD + d];
    g_pts[g] = make_float4(xr[0], xr[1], xr[2],
                           xr[0]*xr[0] + xr[1]*xr[1] + xr[2]*xr[2]);

    float acc[CC];

    // hidden = relu(x @ w1 + b1)
    {
        const float4* bq = (const float4*)b1v;
        #pragma unroll
        for (int c4 = 0; c4 < CC/4; c4++) {
            float4 bv = bq[c4];
            acc[c4*4+0]=bv.x; acc[c4*4+1]=bv.y; acc[c4*4+2]=bv.z; acc[c4*4+3]=bv.w;
        }
        #pragma unroll
        for (int d = 0; d < DD; d++) {
            float xv = xr[d];
            const float4* wv = (const float4*)(w1 + d*CC);
            #pragma unroll
            for (int c4 = 0; c4 < CC/4; c4++) {
                float4 w = wv[c4];
                acc[c4*4+0] = fmaf(xv, w.x, acc[c4*4+0]);
                acc[c4*4+1] = fmaf(xv, w.y, acc[c4*4+1]);
                acc[c4*4+2] = fmaf(xv, w.z, acc[c4*4+2]);
                acc[c4*4+3] = fmaf(xv, w.w, acc[c4*4+3]);
            }
        }
    }
    float hloc[CC];
    #pragma unroll
    for (int c = 0; c < CC; c++) hloc[c] = fmaxf(acc[c], 0.f);

    // feats = hidden @ w2 + b2
    {
        const float4* bq = (const float4*)b2v;
        #pragma unroll
        for (int c4 = 0; c4 < CC/4; c4++) {
            float4 bv = bq[c4];
            acc[c4*4+0]=bv.x; acc[c4*4+1]=bv.y; acc[c4*4+2]=bv.z; acc[c4*4+3]=bv.w;
        }
        #pragma unroll 1
        for (int j = 0; j < CC; j++) {
            float hv = hloc[j];
            const float4* wv = (const float4*)(w2 + j*CC);
            #pragma unroll
            for (int c4 = 0; c4 < CC/4; c4++) {
                float4 w = wv[c4];
                acc[c4*4+0] = fmaf(hv, w.x, acc[c4*4+0]);
                acc[c4*4+1] = fmaf(hv, w.y, acc[c4*4+1]);
                acc[c4*4+2] = fmaf(hv, w.z, acc[c4*4+2]);
                acc[c4*4+3] = fmaf(hv, w.w, acc[c4*4+3]);
            }
        }
    }
    float floc[CC];
    #pragma unroll
    for (int c = 0; c < CC; c++) floc[c] = acc[c];

    // G1 = feats @ f1w
    #pragma unroll
    for (int c = 0; c < CC; c++) acc[c] = 0.f;
    #pragma unroll 1
    for (int j = 0; j < CC; j++) {
        float fv = floc[j];
        const float4* wv = (const float4*)(f1w + j*CC);
        #pragma unroll
        for (int c4 = 0; c4 < CC/4; c4++) {
            float4 w = wv[c4];
            acc[c4*4+0] = fmaf(fv, w.x, acc[c4*4+0]);
            acc[c4*4+1] = fmaf(fv, w.y, acc[c4*4+1]);
            acc[c4*4+2] = fmaf(fv, w.z, acc[c4*4+2]);
            acc[c4*4+3] = fmaf(fv, w.w, acc[c4*4+3]);
        }
    }
    {
        float4* o = (float4*)g_G1 + g*(CC/4);
        #pragma unroll
        for (int c4 = 0; c4 < CC/4; c4++)
            o[c4] = make_float4(acc[c4*4+0], acc[c4*4+1], acc[c4*4+2], acc[c4*4+3]);
    }

    // G2 = feats @ f2w
    #pragma unroll
    for (int c = 0; c < CC; c++) acc[c] = 0.f;
    #pragma unroll 1
    for (int j = 0; j < CC; j++) {
        float fv = floc[j];
        const float4* wv = (const float4*)(f2w + j*CC);
        #pragma unroll
        for (int c4 = 0; c4 < CC/4; c4++) {
            float4 w = wv[c4];
            acc[c4*4+0] = fmaf(fv, w.x, acc[c4*4+0]);
            acc[c4*4+1] = fmaf(fv, w.y, acc[c4*4+1]);
            acc[c4*4+2] = fmaf(fv, w.z, acc[c4*4+2]);
            acc[c4*4+3] = fmaf(fv, w.w, acc[c4*4+3]);
        }
    }
    {
        float4* o = (float4*)g_G2 + g*(CC/4);
        #pragma unroll
        for (int c4 = 0; c4 < CC/4; c4++)
            o[c4] = make_float4(acc[c4*4+0], acc[c4*4+1], acc[c4*4+2], acc[c4*4+3]);
    }
}

// ---------------------------------------------------------------------------
// Exact 32-smallest of buf[0..cnt) via 8x4 group-max insert (first-seen kept
// among equals). Writes survivors to buf[0..32); returns worst (32nd).
// ---------------------------------------------------------------------------
__device__ __noinline__ float compact32(unsigned long long* buf, int cnt,
                                        float* kd, int* ki)
{
    const float INF = inf_f();
    float gm[8];
    #pragma unroll
    for (int i = 0; i < 8; i++) gm[i] = INF;
    #pragma unroll 1
    for (int i = 0; i < KK; i++) { kd[i] = INF; ki[i] = 0; }
    float worst = INF;

    #pragma unroll 1
    for (int tix = 0; tix < cnt; tix++) {
        unsigned long long v = buf[tix];
        float s = __uint_as_float((unsigned)(v >> 32));
        if (s < worst) {
            int id = (int)(unsigned)v;
            int gsel = 0; float gv = gm[0];
            #pragma unroll
            for (int i = 1; i < 8; i++) if (gm[i] > gv) { gv = gm[i]; gsel = i; }
            int base = gsel*4;
            float v0 = kd[base], v1 = kd[base+1], v2 = kd[base+2], v3 = kd[base+3];
            int e = 0; float ev = v0;
            if (v1 > ev) { ev = v1; e = 1; }
            if (v2 > ev) { ev = v2; e = 2; }
            if (v3 > ev) { ev = v3; e = 3; }
            kd[base+e] = s; ki[base+e] = id;
            float ngm = fmaxf(fmaxf(e==0?s:v0, e==1?s:v1),
                              fmaxf(e==2?s:v2, e==3?s:v3));
            #pragma unroll
            for (int i = 0; i < 8; i++) if (i == gsel) gm[i] = ngm;
            float w8 = gm[0];
            #pragma unroll
            for (int i = 1; i < 8; i++) w8 = fmaxf(w8, gm[i]);
            worst = w8;
        }
    }
    #pragma unroll 1
    for (int i = 0; i < KK; i++)
        buf[i] = ((unsigned long long)__float_as_uint(kd[i]) << 32) |
                 (unsigned)ki[i];
    return worst;
}

// ---------------------------------------------------------------------------
// Exact 32-NN, chunk-streamed: candidates pass through a 32KB smem buffer in
// 4 chunks of 2000 (vs 128KB monolithic staging) -> 2-3 blocks/SM instead of
// 1, doubling/tripling warps per scheduler. Work is NOT sliced: each thread
// still scans all 8000 candidates with one threshold lifecycle (thr=INF until
// the first exact compaction), so the result is exactly the 32 smallest.
// Appends: predicated stores + tree-prefix offsets (no branches, no serial
// pointer chain). Compactions warp-synchronized via __any_sync.
// ---------------------------------------------------------------------------
__global__ __launch_bounds__(256) void knn_kernel() {
    __shared__ float4 sp[CHUNK];
    int b = blockIdx.y;
    const float4* src = g_pts + b*NN;

    int q = blockIdx.x * 256 + threadIdx.x;
    if (q >= NN) q = NN - 1;              // clamp (ballot safety)

    float4 me = g_pts[b*NN + q];
    float mx = -2.f*me.x, my = -2.f*me.y, mz = -2.f*me.z;
    const float INF = inf_f();

    unsigned long long buf[CAP];
    float kd[KK]; int ki[KK];
    float thr = INF;
    int cnt = 0;

    #pragma unroll 1
    for (int ch = 0; ch < NN/CHUNK; ch++) {          // 4 chunks
        __syncthreads();                             // previous chunk consumed
        {
            const float4* csrc = src + ch*CHUNK;
            #pragma unroll
            for (int k = 0; k < CHUNK/256; k++) {    // 7 full rounds
                int j = threadIdx.x + k*256;
                sp[j] = csrc[j];
            }
            int j = threadIdx.x + (CHUNK/256)*256;   // remainder (208 lanes)
            if (j < CHUNK) sp[j] = csrc[j];
        }
        __syncthreads();

        int jb = ch*CHUNK;
        #pragma unroll 1
        for (int jo = 0; jo < CHUNK/40; jo++) {      // 50 iters x 40 cands
            #pragma unroll 1
            for (int gi = 0; gi < 5; gi++) {
                int j0 = jo*40 + gi*8;
                float s[8];
                #pragma unroll
                for (int u = 0; u < 8; u++) {
                    float4 c = sp[j0 + u];
                    float ss = fmaf(c.x, mx, c.w);
                    ss = fmaf(c.y, my, ss);
                    s[u] = fmaf(c.z, mz, ss);
                }
                // predicates + tree-prefix offsets (independent stores)
                int e0 = (s[0] < thr) ? 1 : 0;
                int e1 = (s[1] < thr) ? 1 : 0;
                int e2 = (s[2] < thr) ? 1 : 0;
                int e3 = (s[3] < thr) ? 1 : 0;
                int e4 = (s[4] < thr) ? 1 : 0;
                int e5 = (s[5] < thr) ? 1 : 0;
                int e6 = (s[6] < thr) ? 1 : 0;
                int e7 = (s[7] < thr) ? 1 : 0;
                int t01 = e0 + e1, t23 = e2 + e3, t45 = e4 + e5, t67 = e6 + e7;
                int t03 = t01 + t23, t47 = t45 + t67;
                int o1 = e0;
                int o2 = t01;
                int o3 = t01 + e2;
                int o4 = t03;
                int o5 = t03 + e4;
                int o6 = t03 + t45;
                int o7 = t03 + t45 + e6;
                int tot = t03 + t47;
                #pragma unroll
                for (int u = 0; u < 8; u++) {
                    int off;
                    switch (u) {
                        case 0: off = 0;  break;
                        case 1: off = o1; break;
                        case 2: off = o2; break;
                        case 3: off = o3; break;
                        case 4: off = o4; break;
                        case 5: off = o5; break;
                        case 6: off = o6; break;
                        default: off = o7; break;
                    }
                    unsigned long long pk =
                        ((unsigned long long)__float_as_uint(s[u]) << 32)
                        | (unsigned)(jb + j0 + u);
                    if (s[u] < thr) buf[cnt + off] = pk;   // @P STL.64
                }
                cnt += tot;
            }
            if (__any_sync(0xffffffffu, cnt >= CAP - 40)) {
                float w2 = compact32(buf, cnt, kd, ki);
                thr = fminf(thr, w2);
                cnt = KK;
            }
        }
    }

    compact32(buf, cnt, kd, ki);           // cnt >= 32 always
    int* o = g_idx + (b*NN + q)*KK;
    #pragma unroll 1
    for (int i = 0; i < KK; i++) o[i] = ki[i];
}

// ---------------------------------------------------------------------------
// Fuse (both branches) + classifier. msg = relu(G[nbr]-G[i]+b); max over K;
// fused = m1+m2; then 64->32->13 MLP. 4 points/block, 64 channel-threads.
// ---------------------------------------------------------------------------
__global__ __launch_bounds__(256) void fuse_kernel(
    const float* __restrict__ f1b, const float* __restrict__ f2b,
    const float* __restrict__ cw1, const float* __restrict__ cb1,
    const float* __restrict__ cw2, const float* __restrict__ cb2,
    float* __restrict__ out)
{
    __shared__ float sfused[4][CC];
    __shared__ float shid[4][CC/2];
    __shared__ int   sidx[4][KK];

    int tid = threadIdx.x;
    int p = tid >> 6, c = tid & 63;
    int g = blockIdx.x*4 + p;

    if (c < KK) sidx[p][c] = g_idx[g*KK + c];
    __syncthreads();

    int b = g / NN;
    int rowbase = b*NN;

    float g1i = g_G1[g*CC + c];
    float g2i = g_G2[g*CC + c];
    float bb1 = f1b[c] - g1i;
    float bb2 = f2b[c] - g2i;
    float m1 = 0.f, m2 = 0.f;
    #pragma unroll 8
    for (int k = 0; k < KK; k++) {
        int j = sidx[p][k] + rowbase;
        m1 = fmaxf(m1, g_G1[j*CC + c] + bb1);
        m2 = fmaxf(m2, g_G2[j*CC + c] + bb2);
    }
    sfused[p][c] = m1 + m2;
    __syncthreads();

    if (c < CC/2) {
        float a = cb1[c];
        #pragma unroll
        for (int u = 0; u < CC; u++) a = fmaf(sfused[p][u], cw1[u*(CC/2) + c], a);
        shid[p][c] = fmaxf(a, 0.f);
    }
    __syncthreads();

    if (c < NCLS) {
        float a = cb2[c];
        #pragma unroll
        for (int u = 0; u < CC/2; u++) a = fmaf(shid[p][u], cw2[u*NCLS + c], a);
        out[g*NCLS + c] = a;
    }
}

extern "C" void kernel_launch(void* const* d_in, const int* in_sizes, int n_in,
                              void* d_out, int out_size) {
    const float* x      = (const float*)d_in[0];
    const float* enc_w1 = (const float*)d_in[1];
    const float* enc_b1 = (const float*)d_in[2];
    const float* enc_w2 = (const float*)d_in[3];
    const float* enc_b2 = (const float*)d_in[4];
    const float* f1_w   = (const float*)d_in[5];
    const float* f1_b   = (const float*)d_in[6];
    const float* f2_w   = (const float*)d_in[7];
    const float* f2_b   = (const float*)d_in[8];
    const float* cls_w1 = (const float*)d_in[9];
    const float* cls_b1 = (const float*)d_in[10];
    const float* cls_w2 = (const float*)d_in[11];
    const float* cls_b2 = (const float*)d_in[12];

    encoder_kernel<<<(BN + 255)/256, 256>>>(x, enc_w1, enc_b1, enc_w2, enc_b2,
                                            f1_w, f2_w);

    dim3 kg((NN + 255)/256, BB);
    knn_kernel<<<kg, 256>>>();

    fuse_kernel<<<BN/4, 256>>>(f1_b, f2_b, cls_w1, cls_b1, cls_w2, cls_b2,
                               (float*)d_out);
}

// round 11
// speedup vs baseline: 1.2184x; 1.2184x over previous
#include <cuda_runtime.h>

#define BB   4
#define NN   8000
#define CC   64
#define KK   32
#define DD   9
#define NCLS 13
#define BN   (BB*NN)

#define CAP  128          // per-thread candidate buffer slots (1KB local)

__device__ float  g_G1[BN*CC];
__device__ float  g_G2[BN*CC];
__device__ float4 g_pts[BN];
__device__ int    g_idx[BN*KK];

__device__ __forceinline__ float inf_f() { return __int_as_float(0x7f800000); }

// ---------------------------------------------------------------------------
// Encoder (measured-best: block=256, 161 regs, 101us):
// feats = relu(x@w1+b1)@w2+b2 ; G1 = feats@f1w ; G2 = feats@f2w
// ---------------------------------------------------------------------------
__global__ __launch_bounds__(256) void encoder_kernel(
    const float* __restrict__ x,
    const float* __restrict__ w1, const float* __restrict__ b1v,
    const float* __restrict__ w2, const float* __restrict__ b2v,
    const float* __restrict__ f1w, const float* __restrict__ f2w)
{
    int g = blockIdx.x * blockDim.x + threadIdx.x;
    if (g >= BN) return;

    float xr[DD];
    #pragma unroll
    for (int d = 0; d < DD; d++) xr[d] = x[g*DD + d];
    g_pts[g] = make_float4(xr[0], xr[1], xr[2],
                           xr[0]*xr[0] + xr[1]*xr[1] + xr[2]*xr[2]);

    float acc[CC];

    // hidden = relu(x @ w1 + b1)
    {
        const float4* bq = (const float4*)b1v;
        #pragma unroll
        for (int c4 = 0; c4 < CC/4; c4++) {
            float4 bv = bq[c4];
            acc[c4*4+0]=bv.x; acc[c4*4+1]=bv.y; acc[c4*4+2]=bv.z; acc[c4*4+3]=bv.w;
        }
        #pragma unroll
        for (int d = 0; d < DD; d++) {
            float xv = xr[d];
            const float4* wv = (const float4*)(w1 + d*CC);
            #pragma unroll
            for (int c4 = 0; c4 < CC/4; c4++) {
                float4 w = wv[c4];
                acc[c4*4+0] = fmaf(xv, w.x, acc[c4*4+0]);
                acc[c4*4+1] = fmaf(xv, w.y, acc[c4*4+1]);
                acc[c4*4+2] = fmaf(xv, w.z, acc[c4*4+2]);
                acc[c4*4+3] = fmaf(xv, w.w, acc[c4*4+3]);
            }
        }
    }
    float hloc[CC];
    #pragma unroll
    for (int c = 0; c < CC; c++) hloc[c] = fmaxf(acc[c], 0.f);

    // feats = hidden @ w2 + b2
    {
        const float4* bq = (const float4*)b2v;
        #pragma unroll
        for (int c4 = 0; c4 < CC/4; c4++) {
            float4 bv = bq[c4];
            acc[c4*4+0]=bv.x; acc[c4*4+1]=bv.y; acc[c4*4+2]=bv.z; acc[c4*4+3]=bv.w;
        }
        #pragma unroll 1
        for (int j = 0; j < CC; j++) {
            float hv = hloc[j];
            const float4* wv = (const float4*)(w2 + j*CC);
            #pragma unroll
            for (int c4 = 0; c4 < CC/4; c4++) {
                float4 w = wv[c4];
                acc[c4*4+0] = fmaf(hv, w.x, acc[c4*4+0]);
                acc[c4*4+1] = fmaf(hv, w.y, acc[c4*4+1]);
                acc[c4*4+2] = fmaf(hv, w.z, acc[c4*4+2]);
                acc[c4*4+3] = fmaf(hv, w.w, acc[c4*4+3]);
            }
        }
    }
    float floc[CC];
    #pragma unroll
    for (int c = 0; c < CC; c++) floc[c] = acc[c];

    // G1 = feats @ f1w
    #pragma unroll
    for (int c = 0; c < CC; c++) acc[c] = 0.f;
    #pragma unroll 1
    for (int j = 0; j < CC; j++) {
        float fv = floc[j];
        const float4* wv = (const float4*)(f1w + j*CC);
        #pragma unroll
        for (int c4 = 0; c4 < CC/4; c4++) {
            float4 w = wv[c4];
            acc[c4*4+0] = fmaf(fv, w.x, acc[c4*4+0]);
            acc[c4*4+1] = fmaf(fv, w.y, acc[c4*4+1]);
            acc[c4*4+2] = fmaf(fv, w.z, acc[c4*4+2]);
            acc[c4*4+3] = fmaf(fv, w.w, acc[c4*4+3]);
        }
    }
    {
        float4* o = (float4*)g_G1 + g*(CC/4);
        #pragma unroll
        for (int c4 = 0; c4 < CC/4; c4++)
            o[c4] = make_float4(acc[c4*4+0], acc[c4*4+1], acc[c4*4+2], acc[c4*4+3]);
    }

    // G2 = feats @ f2w
    #pragma unroll
    for (int c = 0; c < CC; c++) acc[c] = 0.f;
    #pragma unroll 1
    for (int j = 0; j < CC; j++) {
        float fv = floc[j];
        const float4* wv = (const float4*)(f2w + j*CC);
        #pragma unroll
        for (int c4 = 0; c4 < CC/4; c4++) {
            float4 w = wv[c4];
            acc[c4*4+0] = fmaf(fv, w.x, acc[c4*4+0]);
            acc[c4*4+1] = fmaf(fv, w.y, acc[c4*4+1]);
            acc[c4*4+2] = fmaf(fv, w.z, acc[c4*4+2]);
            acc[c4*4+3] = fmaf(fv, w.w, acc[c4*4+3]);
        }
    }
    {
        float4* o = (float4*)g_G2 + g*(CC/4);
        #pragma unroll
        for (int c4 = 0; c4 < CC/4; c4++)
            o[c4] = make_float4(acc[c4*4+0], acc[c4*4+1], acc[c4*4+2], acc[c4*4+3]);
    }
}

// ---------------------------------------------------------------------------
// Exact 32-smallest of buf[0..cnt) via 8x4 group-max insert (first-seen kept
// among equals). Writes survivors to buf[0..32); returns worst (32nd).
// ---------------------------------------------------------------------------
__device__ __noinline__ float compact32(unsigned long long* buf, int cnt,
                                        float* kd, int* ki)
{
    const float INF = inf_f();
    float gm[8];
    #pragma unroll
    for (int i = 0; i < 8; i++) gm[i] = INF;
    #pragma unroll 1
    for (int i = 0; i < KK; i++) { kd[i] = INF; ki[i] = 0; }
    float worst = INF;

    #pragma unroll 1
    for (int tix = 0; tix < cnt; tix++) {
        unsigned long long v = buf[tix];
        float s = __uint_as_float((unsigned)(v >> 32));
        if (s < worst) {
            int id = (int)(unsigned)v;
            int gsel = 0; float gv = gm[0];
            #pragma unroll
            for (int i = 1; i < 8; i++) if (gm[i] > gv) { gv = gm[i]; gsel = i; }
            int base = gsel*4;
            float v0 = kd[base], v1 = kd[base+1], v2 = kd[base+2], v3 = kd[base+3];
            int e = 0; float ev = v0;
            if (v1 > ev) { ev = v1; e = 1; }
            if (v2 > ev) { ev = v2; e = 2; }
            if (v3 > ev) { ev = v3; e = 3; }
            kd[base+e] = s; ki[base+e] = id;
            float ngm = fmaxf(fmaxf(e==0?s:v0, e==1?s:v1),
                              fmaxf(e==2?s:v2, e==3?s:v3));
            #pragma unroll
            for (int i = 0; i < 8; i++) if (i == gsel) gm[i] = ngm;
            float w8 = gm[0];
            #pragma unroll
            for (int i = 1; i < 8; i++) w8 = fmaxf(w8, gm[i]);
            worst = w8;
        }
    }
    #pragma unroll 1
    for (int i = 0; i < KK; i++)
        buf[i] = ((unsigned long long)__float_as_uint(kd[i]) << 32) |
                 (unsigned)ki[i];
    return worst;
}

// ---------------------------------------------------------------------------
// Exact 32-NN (measured-best R9 structure: monolithic 128KB smem staging +
// tree-prefix predicated appends). s = |pj|^2 - 2 pi.pj (order-preserving
// shift of sq-distance). thr starts at INF so the first compaction -- and
// the final result -- is exact. Compactions warp-synchronized (__any_sync
// on a warp-uniform loop).
// ---------------------------------------------------------------------------
__global__ __launch_bounds__(256) void knn_kernel() {
    extern __shared__ float4 sp[];
    int b = blockIdx.y;
    for (int j = threadIdx.x; j < NN; j += 256) sp[j] = g_pts[b*NN + j];
    __syncthreads();

    int q = blockIdx.x * 256 + threadIdx.x;
    if (q >= NN) q = NN - 1;              // clamp (ballot safety)

    float4 me = sp[q];
    float mx = -2.f*me.x, my = -2.f*me.y, mz = -2.f*me.z;
    const float INF = inf_f();

    unsigned long long buf[CAP];
    float kd[KK]; int ki[KK];
    float thr = INF;
    int cnt = 0;

    #pragma unroll 1
    for (int jo = 0; jo < NN/32; jo++) {   // 250 outer iterations
        #pragma unroll 1
        for (int gi = 0; gi < 4; gi++) {
            int j0 = jo*32 + gi*8;
            float s[8];
            #pragma unroll
            for (int u = 0; u < 8; u++) {
                float4 c = sp[j0 + u];
                float ss = fmaf(c.x, mx, c.w);
                ss = fmaf(c.y, my, ss);
                s[u] = fmaf(c.z, mz, ss);
            }
            // predicates + tree-prefix offsets (independent stores)
            int e0 = (s[0] < thr) ? 1 : 0;
            int e1 = (s[1] < thr) ? 1 : 0;
            int e2 = (s[2] < thr) ? 1 : 0;
            int e3 = (s[3] < thr) ? 1 : 0;
            int e4 = (s[4] < thr) ? 1 : 0;
            int e5 = (s[5] < thr) ? 1 : 0;
            int e6 = (s[6] < thr) ? 1 : 0;
            int e7 = (s[7] < thr) ? 1 : 0;
            int t01 = e0 + e1, t23 = e2 + e3, t45 = e4 + e5, t67 = e6 + e7;
            int t03 = t01 + t23, t47 = t45 + t67;
            int o1 = e0;
            int o2 = t01;
            int o3 = t01 + e2;
            int o4 = t03;
            int o5 = t03 + e4;
            int o6 = t03 + t45;
            int o7 = t03 + t45 + e6;
            int tot = t03 + t47;
            #pragma unroll
            for (int u = 0; u < 8; u++) {
                int off;
                switch (u) {               // compile-time resolved
                    case 0: off = 0;  break;
                    case 1: off = o1; break;
                    case 2: off = o2; break;
                    case 3: off = o3; break;
                    case 4: off = o4; break;
                    case 5: off = o5; break;
                    case 6: off = o6; break;
                    default: off = o7; break;
                }
                unsigned long long pk =
                    ((unsigned long long)__float_as_uint(s[u]) << 32)
                    | (unsigned)(j0 + u);
                if (s[u] < thr) buf[cnt + off] = pk;   // @P STL.64
            }
            cnt += tot;
        }
        if (__any_sync(0xffffffffu, cnt >= CAP - 32)) {
            float w2 = compact32(buf, cnt, kd, ki);
            thr = fminf(thr, w2);
            cnt = KK;
        }
    }

    compact32(buf, cnt, kd, ki);           // cnt >= 32 always
    int* o = g_idx + (b*NN + q)*KK;
    #pragma unroll 1
    for (int i = 0; i < KK; i++) o[i] = ki[i];
}

// ---------------------------------------------------------------------------
// Fuse (both branches) + classifier. msg = relu(G[nbr]-G[i]+b); max over K;
// fused = m1+m2; then 64->32->13 MLP. 4 points/block, 64 channel-threads.
// ---------------------------------------------------------------------------
__global__ __launch_bounds__(256) void fuse_kernel(
    const float* __restrict__ f1b, const float* __restrict__ f2b,
    const float* __restrict__ cw1, const float* __restrict__ cb1,
    const float* __restrict__ cw2, const float* __restrict__ cb2,
    float* __restrict__ out)
{
    __shared__ float sfused[4][CC];
    __shared__ float shid[4][CC/2];
    __shared__ int   sidx[4][KK];

    int tid = threadIdx.x;
    int p = tid >> 6, c = tid & 63;
    int g = blockIdx.x*4 + p;

    if (c < KK) sidx[p][c] = g_idx[g*KK + c];
    __syncthreads();

    int b = g / NN;
    int rowbase = b*NN;

    float g1i = g_G1[g*CC + c];
    float g2i = g_G2[g*CC + c];
    float bb1 = f1b[c] - g1i;
    float bb2 = f2b[c] - g2i;
    float m1 = 0.f, m2 = 0.f;
    #pragma unroll 8
    for (int k = 0; k < KK; k++) {
        int j = sidx[p][k] + rowbase;
        m1 = fmaxf(m1, g_G1[j*CC + c] + bb1);
        m2 = fmaxf(m2, g_G2[j*CC + c] + bb2);
    }
    sfused[p][c] = m1 + m2;
    __syncthreads();

    if (c < CC/2) {
        float a = cb1[c];
        #pragma unroll
        for (int u = 0; u < CC; u++) a = fmaf(sfused[p][u], cw1[u*(CC/2) + c], a);
        shid[p][c] = fmaxf(a, 0.f);
    }
    __syncthreads();

    if (c < NCLS) {
        float a = cb2[c];
        #pragma unroll
        for (int u = 0; u < CC/2; u++) a = fmaf(shid[p][u], cw2[u*NCLS + c], a);
        out[g*NCLS + c] = a;
    }
}

extern "C" void kernel_launch(void* const* d_in, const int* in_sizes, int n_in,
                              void* d_out, int out_size) {
    const float* x      = (const float*)d_in[0];
    const float* enc_w1 = (const float*)d_in[1];
    const float* enc_b1 = (const float*)d_in[2];
    const float* enc_w2 = (const float*)d_in[3];
    const float* enc_b2 = (const float*)d_in[4];
    const float* f1_w   = (const float*)d_in[5];
    const float* f1_b   = (const float*)d_in[6];
    const float* f2_w   = (const float*)d_in[7];
    const float* f2_b   = (const float*)d_in[8];
    const float* cls_w1 = (const float*)d_in[9];
    const float* cls_b1 = (const float*)d_in[10];
    const float* cls_w2 = (const float*)d_in[11];
    const float* cls_b2 = (const float*)d_in[12];

    encoder_kernel<<<(BN + 255)/256, 256>>>(x, enc_w1, enc_b1, enc_w2, enc_b2,
                                            f1_w, f2_w);

    const int knn_smem = NN * (int)sizeof(float4);   // 128000 B
    cudaFuncSetAttribute(knn_kernel, cudaFuncAttributeMaxDynamicSharedMemorySize,
                         knn_smem);
    dim3 kg((NN + 255)/256, BB);
    knn_kernel<<<kg, 256, knn_smem>>>();

    fuse_kernel<<<BN/4, 256>>>(f1_b, f2_b, cls_w1, cls_b1, cls_w2, cls_b2,
                               (float*)d_out);
}